// round 11
// baseline (speedup 1.0000x reference)
#include <cuda_runtime.h>
#include <math.h>

#define E 64
#define CHUNK 64                       // tokens per routing chunk
#define MAX_TOK 16384
#define MAX_CHUNKS (MAX_TOK / CHUNK)

// Scratch (no allocations allowed)
__device__ int   g_idx[MAX_TOK];
__device__ float g_gate[MAX_TOK];
__device__ int   g_slot[MAX_TOK];
__device__ int   g_hist[MAX_CHUNKS * E];

// ---------------------------------------------------------------------------
// K1: zero BOTH tensors' rows for the upper half of tokens + embedded
// routing for ALL tokens. 80 KB/block two-stream pattern (84% DRAM proven).
// grid = s - half. Block b owns token half+b. Blocks b < nchunks route
// chunk b first (hidden under the store storm).
// ---------------------------------------------------------------------------
__global__ void fill_hi_route_kernel(const float* __restrict__ in,
                                     float* __restrict__ out,
                                     size_t sec, int row, int s, int half,
                                     int nchunks, int write_mask) {
    __shared__ int hist[E];

    int b   = blockIdx.x;
    int tid = threadIdx.x;             // 0..255

    if (b < nchunks) {
        if (tid < E) hist[tid] = 0;

        int t_local = tid >> 2;        // token within chunk 0..63
        int quad    = tid & 3;         // 16-expert slice
        int token   = b * CHUNK + t_local;
        bool valid  = (token < s);
        int  tok_c  = valid ? token : (s - 1);

        const float4* p4 = (const float4*)(in + (size_t)tok_c * E + quad * 16);
        float4 va = p4[0], vb = p4[1], vc = p4[2], vd = p4[3];
        float v[16] = {va.x, va.y, va.z, va.w, vb.x, vb.y, vb.z, vb.w,
                       vc.x, vc.y, vc.z, vc.w, vd.x, vd.y, vd.z, vd.w};

        float m = v[0];
        int   am = quad * 16;
#pragma unroll
        for (int k = 1; k < 16; k++)
            if (v[k] > m) { m = v[k]; am = quad * 16 + k; }
#pragma unroll
        for (int off = 1; off < 4; off <<= 1) {
            float mo = __shfl_xor_sync(0xffffffffu, m, off);
            int   ao = __shfl_xor_sync(0xffffffffu, am, off);
            if (mo > m || (mo == m && ao < am)) { m = mo; am = ao; }
        }
        float sum = 0.f;
#pragma unroll
        for (int k = 0; k < 16; k++) sum += __expf(v[k] - m);
#pragma unroll
        for (int off = 1; off < 4; off <<= 1)
            sum += __shfl_xor_sync(0xffffffffu, sum, off);

        __syncthreads();               // hist zeroed
        if (valid && quad == 0) {
            g_idx[token]  = am;
            g_gate[token] = 1.0f / sum;
            atomicAdd(&hist[am], 1);
        }
        __syncthreads();
        if (tid < E) g_hist[b * E + tid] = hist[tid];
        // visibility to K2: kernel boundary. No fence.
    }

    // zero token (half+b)'s rows in BOTH tensors: two 40KB streams = 80KB
    int t  = half + b;
    int n4 = row >> 2;
    float4* __restrict__ c4 = (float4*)(out + (size_t)t * row);
    float4* __restrict__ m4 = (float4*)(out + sec + (size_t)t * row);
    float4 z = make_float4(0.f, 0.f, 0.f, 0.f);

    if (write_mask) {
        for (int i = tid; i < n4; i += blockDim.x) {
            __stcs(&c4[i], z);
            __stcs(&m4[i], z);
        }
    } else {
        for (int i = tid; i < n4; i += blockDim.x)
            __stcs(&c4[i], z);
    }
}

// ---------------------------------------------------------------------------
// K2: cross-chunk exclusive prefix + in-chunk rank -> g_slot (proven ~1.5us).
// grid = nchunks, 128 threads; full hist table in dynamic smem.
// ---------------------------------------------------------------------------
__global__ void prefix_slot_kernel(int s, int cap, int nchunks) {
    extern __shared__ int hist_sh[];          // nchunks * E ints (32 KB)
    __shared__ int base_sh[E];
    __shared__ int idx_sh[CHUNK];
    __shared__ int w0cnt[E];

    int blk = blockIdx.x;
    int tid = threadIdx.x;                    // 0..127

    int total = nchunks * E;
    for (int i = tid; i < total; i += 128) hist_sh[i] = g_hist[i];
    if (tid < E) w0cnt[tid] = 0;

    int base = blk * CHUNK;
    int tokens = s - base;
    if (tokens > CHUNK) tokens = CHUNK;
    if (tid < tokens) idx_sh[tid] = g_idx[base + tid];
    __syncthreads();

    if (tid < E) {
        int r = 0;
        for (int c = 0; c < blk; c++) r += hist_sh[c * E + tid];
        base_sh[tid] = r;
    }
    __syncthreads();

    int e = (tid < tokens) ? idx_sh[tid] : -1;
    unsigned mask = __match_any_sync(0xffffffffu, e);
    int lane   = tid & 31;
    int within = __popc(mask & ((1u << lane) - 1));
    if (tid < 32 && within == 0 && e >= 0) w0cnt[e] = __popc(mask);
    __syncthreads();

    if (tid < tokens && e >= 0) {
        int r = base_sh[e] + within + ((tid >= 32) ? w0cnt[e] : 0);
        g_slot[base + tid] = (r < cap) ? (e * cap + r) : -1;
    }
}

// ---------------------------------------------------------------------------
// K3: zero BOTH tensors' rows for the lower half of tokens (80 KB/block),
// hot in-block fixup for token b, plus scattered fixup for token half+b
// (2 fire-and-forget stores hidden under ~46us of streaming stores).
// ---------------------------------------------------------------------------
__global__ void fill_lo_fix_kernel(float* __restrict__ out, size_t sec,
                                   int row, int s, int half, int write_mask) {
    int b   = blockIdx.x;              // token b in [0, half)
    int tid = threadIdx.x;

    int n4 = row >> 2;
    float4* __restrict__ c4 = (float4*)(out + (size_t)b * row);
    float4* __restrict__ m4 = (float4*)(out + sec + (size_t)b * row);
    float4 z = make_float4(0.f, 0.f, 0.f, 0.f);

    if (write_mask) {
        for (int i = tid; i < n4; i += blockDim.x) {
            __stcs(&c4[i], z);
            __stcs(&m4[i], z);
        }
    } else {
        for (int i = tid; i < n4; i += blockDim.x)
            __stcs(&c4[i], z);
    }
    __syncthreads();                   // order own zeros before hot fixup

    if (tid == 0) {
        // hot fixup: lines this block just wrote
        int p = g_slot[b];
        if (p >= 0) {
            out[(size_t)b * row + (size_t)p] = g_gate[b];
            if (write_mask) out[sec + (size_t)b * row + (size_t)p] = 1.0f;
        }
    } else if (tid == 32) {
        // scattered fixup for the upper-half partner token (zeroed in K1)
        int t2 = half + b;
        if (t2 < s) {
            int p = g_slot[t2];
            if (p >= 0) {
                out[(size_t)t2 * row + (size_t)p] = g_gate[t2];
                if (write_mask) out[sec + (size_t)t2 * row + (size_t)p] = 1.0f;
            }
        }
    }
}

// ---------------------------------------------------------------------------
// Tail: zero anything beyond the two tensors (output poisoned 0xAA)
// ---------------------------------------------------------------------------
__global__ void tail_zero(float* __restrict__ out, size_t start, size_t end) {
    size_t i = start + blockIdx.x * (size_t)blockDim.x + threadIdx.x;
    size_t stride = gridDim.x * (size_t)blockDim.x;
    for (; i < end; i += stride) out[i] = 0.f;
}

// ---------------------------------------------------------------------------
extern "C" void kernel_launch(void* const* d_in, const int* in_sizes, int n_in,
                              void* d_out, int out_size) {
    const float* in = (const float*)d_in[0];
    float* out = (float*)d_out;

    int total = in_sizes[0];
    int s = total / E;
    int cap = (int)floor(1.25 * (double)s / (double)E);
    cap += (cap & 1);
    if (cap < 4) cap = 4;

    int row = E * cap;
    size_t sec = (size_t)s * (size_t)row;
    int write_mask = ((size_t)out_size >= 2 * sec) ? 1 : 0;

    int nchunks = (s + CHUNK - 1) / CHUNK;
    int half = (s + 1) / 2;            // K3 covers [0,half), K1 covers [half,s)

    // K1: zero upper-half tokens (both tensors) + embedded routing
    int g1 = s - half;
    if (g1 < nchunks) g1 = nchunks;    // ensure all routing blocks exist
    fill_hi_route_kernel<<<g1, 256>>>(in, out, sec, row, s, half, nchunks,
                                      write_mask);

    // K2: prefix + slots (the only exposed prologue piece, ~1.5us)
    size_t smem_bytes = (size_t)nchunks * E * sizeof(int);
    if (smem_bytes > 48 * 1024) {
        cudaFuncSetAttribute(prefix_slot_kernel,
                             cudaFuncAttributeMaxDynamicSharedMemorySize,
                             (int)smem_bytes);
    }
    prefix_slot_kernel<<<nchunks, 128, smem_bytes>>>(s, cap, nchunks);

    // K3: zero lower-half tokens (both tensors) + hot fixup + partner fixup
    fill_lo_fix_kernel<<<half, 256>>>(out, sec, row, s, half, write_mask);

    // tail beyond 2*sec, if any
    size_t covered = write_mask ? 2 * sec : sec;
    if ((size_t)out_size > covered) {
        tail_zero<<<256, 256>>>(out, covered, (size_t)out_size);
    }
}

// round 12
// speedup vs baseline: 1.0503x; 1.0503x over previous
#include <cuda_runtime.h>
#include <math.h>

#define E 64
#define TOK_PER_BLK 128
#define MAX_TOK 16384
#define MAX_CHUNKS (MAX_TOK / TOK_PER_BLK)

// Scratch (no allocations allowed)
__device__ int   g_idx[MAX_TOK];      // per-token argmax expert
__device__ float g_gate[MAX_TOK];     // per-token softmax prob at argmax
__device__ int   g_slot[MAX_TOK];     // per-token flat slot e*cap+r, or -1
__device__ int   g_hist[MAX_CHUNKS * E];

// ---------------------------------------------------------------------------
// Fast exp for d <= 0: exp(d) = 2^(d*log2e) via degree-5 poly + exponent
// bit-trick. Pure FMA/ALU pipe (no MUFU). Rel. error ~1e-7.
// ---------------------------------------------------------------------------
__device__ __forceinline__ float fast_exp_neg(float d) {
    float t = d * 1.442695040888963f;      // log2(e)
    float n = floorf(t);                   // n <= 0
    float f = t - n;                       // f in [0,1)
    float p = 1.3333558146e-3f;
    p = fmaf(p, f, 9.6181291076e-3f);
    p = fmaf(p, f, 5.5504108664e-2f);
    p = fmaf(p, f, 2.4022650695e-1f);
    p = fmaf(p, f, 6.9314718055e-1f);
    p = fmaf(p, f, 1.0f);
    int ni = (int)n;
    ni = (ni < -126) ? -126 : ni;          // underflow clamp (result ~0 anyway)
    float scale = __int_as_float((ni + 127) << 23);
    return p * scale;
}

// ---------------------------------------------------------------------------
// Kernel 1: per-token argmax + softmax prob at argmax + per-chunk histogram.
// 4 threads per token (16 experts each), shfl-combined. 512 thr -> 128 tok.
// ---------------------------------------------------------------------------
__global__ void route_kernel(const float* __restrict__ in, int s) {
    __shared__ int hist[E];

    int blk     = blockIdx.x;
    int tid     = threadIdx.x;        // 0..511
    int t_local = tid >> 2;           // token within chunk 0..127
    int part    = tid & 3;            // 16-expert slice
    int token   = blk * TOK_PER_BLK + t_local;
    bool valid  = (token < s);
    int  tok_c  = valid ? token : (s - 1);

    if (tid < E) hist[tid] = 0;

    const float4* p4 = (const float4*)(in + (size_t)tok_c * E + part * 16);
    float4 a = p4[0], b = p4[1], c = p4[2], d = p4[3];
    float v[16] = {a.x, a.y, a.z, a.w, b.x, b.y, b.z, b.w,
                   c.x, c.y, c.z, c.w, d.x, d.y, d.z, d.w};

    // local first-index argmax over this thread's 16
    float m = v[0];
    int   am = part * 16;
#pragma unroll
    for (int k = 1; k < 16; k++)
        if (v[k] > m) { m = v[k]; am = part * 16 + k; }
#pragma unroll
    for (int off = 1; off < 4; off <<= 1) {
        float mo = __shfl_xor_sync(0xffffffffu, m, off);
        int   ao = __shfl_xor_sync(0xffffffffu, am, off);
        if (mo > m || (mo == m && ao < am)) { m = mo; am = ao; }
    }
    // sum of exp(x - m): FMA-pipe polynomial exp (MUFU was the 4us floor)
    float sum = 0.f;
#pragma unroll
    for (int k = 0; k < 16; k++) sum += fast_exp_neg(v[k] - m);
#pragma unroll
    for (int off = 1; off < 4; off <<= 1)
        sum += __shfl_xor_sync(0xffffffffu, sum, off);

    __syncthreads();                  // hist zeroed
    if (valid && part == 0) {
        g_idx[token]  = am;
        g_gate[token] = 1.0f / sum;
        atomicAdd(&hist[am], 1);
    }
    __syncthreads();
    if (tid < E) g_hist[blk * E + tid] = hist[tid];
}

// ---------------------------------------------------------------------------
// Kernel 2: fused cross-chunk prefix + per-token rank -> g_slot (R3-proven).
// ---------------------------------------------------------------------------
__global__ void prefix_slot_kernel(int s, int cap, int nchunks) {
    extern __shared__ int hist_sh[];          // nchunks * E ints
    __shared__ int base_sh[E];
    __shared__ int idx_sh[TOK_PER_BLK];
    __shared__ int warp_cnt[4][E + 1];

    int blk = blockIdx.x;
    int tid = threadIdx.x;            // 128
    int total = nchunks * E;
    for (int i = tid; i < total; i += TOK_PER_BLK) hist_sh[i] = g_hist[i];
    for (int i = tid; i < 4 * (E + 1); i += TOK_PER_BLK)
        ((int*)warp_cnt)[i] = 0;

    int base = blk * TOK_PER_BLK;
    int tokens = s - base;
    if (tokens > TOK_PER_BLK) tokens = TOK_PER_BLK;
    if (tid < tokens) idx_sh[tid] = g_idx[base + tid];
    __syncthreads();

    if (tid < E) {
        int r = 0;
        for (int c = 0; c < blk; c++) r += hist_sh[c * E + tid];
        base_sh[tid] = r;
    }

    int e = (tid < tokens) ? idx_sh[tid] : E;     // E = dummy bucket
    unsigned mask = __match_any_sync(0xffffffffu, e);
    int lane   = tid & 31;
    int w      = tid >> 5;
    int within = __popc(mask & ((1u << lane) - 1));
    if (within == 0) warp_cnt[w][e] = __popc(mask);
    __syncthreads();

    if (tid < tokens) {
        int r = base_sh[e] + within;
#pragma unroll
        for (int w2 = 0; w2 < 4; w2++)
            if (w2 < w) r += warp_cnt[w2][e];
        g_slot[base + tid] = (r < cap) ? (e * cap + r) : -1;
    }
}

// ---------------------------------------------------------------------------
// Kernel 3: fill (R3-proven 84%-DRAM shape). One block per token;
// streaming zero stores to both tensors, then hot in-block fix-up.
// ---------------------------------------------------------------------------
__global__ void fill_kernel(float* __restrict__ out, size_t sec, int cap,
                            int write_mask) {
    int t   = blockIdx.x;
    int row = E * cap;                // multiple of 4
    int n4  = row >> 2;

    float4* __restrict__ c4 = (float4*)(out + (size_t)t * row);
    float4* __restrict__ m4 = (float4*)(out + sec + (size_t)t * row);
    float4 z = make_float4(0.f, 0.f, 0.f, 0.f);

    if (write_mask) {
        for (int i = threadIdx.x; i < n4; i += blockDim.x) {
            __stcs(&c4[i], z);
            __stcs(&m4[i], z);
        }
    } else {
        for (int i = threadIdx.x; i < n4; i += blockDim.x)
            __stcs(&c4[i], z);
    }
    __syncthreads();

    if (threadIdx.x == 0) {
        int p = g_slot[t];
        if (p >= 0) {
            out[(size_t)t * row + p] = g_gate[t];
            if (write_mask) out[sec + (size_t)t * row + p] = 1.0f;
        }
    }
}

// ---------------------------------------------------------------------------
// Kernel 4: zero any tail beyond the two tensors (output poisoned 0xAA)
// ---------------------------------------------------------------------------
__global__ void tail_zero(float* __restrict__ out, size_t start, size_t end) {
    size_t i = start + blockIdx.x * (size_t)blockDim.x + threadIdx.x;
    size_t stride = gridDim.x * (size_t)blockDim.x;
    for (; i < end; i += stride) out[i] = 0.f;
}

// ---------------------------------------------------------------------------
extern "C" void kernel_launch(void* const* d_in, const int* in_sizes, int n_in,
                              void* d_out, int out_size) {
    const float* in = (const float*)d_in[0];
    float* out = (float*)d_out;

    int total = in_sizes[0];
    int s = total / E;
    int cap = (int)floor(1.25 * (double)s / (double)E);
    cap += (cap & 1);
    if (cap < 4) cap = 4;

    size_t sec = (size_t)s * E * (size_t)cap;
    int write_mask = ((size_t)out_size >= 2 * sec) ? 1 : 0;

    int nchunks = (s + TOK_PER_BLK - 1) / TOK_PER_BLK;

    // 1) router: argmax + gate + per-chunk histogram (FMA-pipe exp)
    route_kernel<<<nchunks, 512>>>(in, s);

    // 2) fused prefix + slot
    size_t smem_bytes = (size_t)nchunks * E * sizeof(int);
    if (smem_bytes > 48 * 1024) {
        cudaFuncSetAttribute(prefix_slot_kernel,
                             cudaFuncAttributeMaxDynamicSharedMemorySize,
                             (int)smem_bytes);
    }
    prefix_slot_kernel<<<nchunks, TOK_PER_BLK, smem_bytes>>>(s, cap, nchunks);

    // 3) streaming fill + hot fix-up
    fill_kernel<<<s, 256>>>(out, sec, cap, write_mask);

    // 4) tail beyond 2*sec, if any
    size_t covered = write_mask ? 2 * sec : sec;
    if ((size_t)out_size > covered) {
        tail_zero<<<256, 256>>>(out, covered, (size_t)out_size);
    }
}